// round 12
// baseline (speedup 1.0000x reference)
#include <cuda_runtime.h>
#include <cuda_bf16.h>
#include <cstdint>

// Problem constants (fixed by the dataset)
#define MAX_NODES 100000
#define D_FEAT    128
#define NPW       8       // nodes per warp-iteration in kernel 1
#define EPT       4       // edges per thread-iteration in kernel 2
#define GRID_BLKS 1184    // 148 SMs x 8 resident 256-thr blocks: 1 full wave
#define QSCALE    4096.0f
#define QINV      (1.0f / 4096.0f)

// Quantized per-node logit-difference table (sigmoid reformulation):
//   dA[n] = emb[n].(W0-W1)[0:128] + (b0-b1),  dB[n] = emb[n].(W0-W1)[128:256]
//   g_dS[n] = (int16 round(dA*4096), int16 round(dB*4096)) packed in 4 bytes.
// Edge e=(r,c): q = qA[r]+qB[c] (exact int), d = q/4096,
//   p0 = 1/(1+exp(-d)), p1 = exp(-d)/(1+exp(-d)).
// Quantization rel err on p ~3e-5 (measured R10/R11).
__device__ unsigned int g_dS[MAX_NODES];

// 1 if edge_index buffer holds int64 elements, 0 if int32.
__device__ int g_idx_is64;

// ---------------------------------------------------------------------------
// Kernel 1: grid-stride; each warp-iteration computes NPW nodes. Lane k owns
// columns 4k..4k+3 (one LDG.128 per node, MLP=NPW). Wd = W0-W1 in smem
// (conflict-free float4 reads). 7-shuffle dual reduction, even lane packs.
// Block 0 / thread 0 also performs the index-dtype detection.
// ---------------------------------------------------------------------------
__global__ __launch_bounds__(256)
void node_scores_kernel(const float4* __restrict__ emb4,
                        const float* __restrict__ W,
                        const float* __restrict__ bias,
                        const unsigned int* __restrict__ idx_words,
                        int n_nodes)
{
    __shared__ __align__(16) float Wd[256];   // W0 - W1, 256 floats
    for (int i = threadIdx.x; i < 256; i += blockDim.x)
        Wd[i] = W[i] - W[256 + i];
    __syncthreads();

    // Index-dtype detection: little-endian int64 ids < 100000 have all odd
    // 32-bit words zero; int32 data has random ids there (P ~ 1e-160).
    if (blockIdx.x == 0 && threadIdx.x == 0) {
        unsigned int acc = 0;
#pragma unroll
        for (int i = 1; i < 64; i += 2) acc |= idx_words[i];
        g_idx_is64 = (acc == 0u) ? 1 : 0;
    }

    const int lane    = threadIdx.x & 31;
    const int warp_g  = (int)((blockIdx.x * (unsigned)blockDim.x + threadIdx.x) >> 5);
    const int n_warps = (GRID_BLKS * 256) >> 5;
    const int n_groups = (n_nodes + NPW - 1) / NPW;

    const float dbias = bias[0] - bias[1];

    const float4* wd4 = (const float4*)Wd;
    const float4 wsrc = wd4[lane];        // (W0-W1)[4k..4k+3]
    const float4 wdst = wd4[32 + lane];   // (W0-W1)[128+4k..128+4k+3]

    for (int grp = warp_g; grp < n_groups; grp += n_warps) {
        const int node0 = grp * NPW;

        // Batch the independent embedding loads first (MLP = NPW).
        float4 v[NPW];
#pragma unroll
        for (int i = 0; i < NPW; i++) {
            const int n = node0 + i;
            v[i] = (n < n_nodes) ? __ldg(&emb4[(size_t)n * 32 + lane])
                                 : make_float4(0.f, 0.f, 0.f, 0.f);
        }

#pragma unroll
        for (int i = 0; i < NPW; i++) {
            float da = v[i].x * wsrc.x;
            da = fmaf(v[i].y, wsrc.y, da);
            da = fmaf(v[i].z, wsrc.z, da);
            da = fmaf(v[i].w, wsrc.w, da);
            float db = v[i].x * wdst.x;
            db = fmaf(v[i].y, wdst.y, db);
            db = fmaf(v[i].z, wdst.z, db);
            db = fmaf(v[i].w, wdst.w, db);

            // Dual reduction: even lanes end with da, odd lanes with db.
            da += __shfl_xor_sync(0xFFFFFFFFu, da, 1);
            db += __shfl_xor_sync(0xFFFFFFFFu, db, 1);
            float sel = (lane & 1) ? db : da;
            sel += __shfl_xor_sync(0xFFFFFFFFu, sel, 2);
            sel += __shfl_xor_sync(0xFFFFFFFFu, sel, 4);
            sel += __shfl_xor_sync(0xFFFFFFFFu, sel, 8);
            sel += __shfl_xor_sync(0xFFFFFFFFu, sel, 16);

            // Bring odd lane's db to the even lane, quantize, pack, store.
            const float other = __shfl_xor_sync(0xFFFFFFFFu, sel, 1);
            const int n = node0 + i;
            if (lane == 2 * i && n < n_nodes) {
                const float dA = sel + dbias;    // even lane held da
                const float dB = other;          // odd lane held db
                int qa = __float2int_rn(fminf(fmaxf(dA * QSCALE, -32767.f), 32767.f));
                int qb = __float2int_rn(fminf(fmaxf(dB * QSCALE, -32767.f), 32767.f));
                g_dS[n] = ((unsigned int)qa & 0xFFFFu) | ((unsigned int)qb << 16);
            }
        }
    }
}

// ---------------------------------------------------------------------------
// Kernel 2: grid-stride; per-edge gather from the L2-resident 400KB packed
// table + sigmoid. EPT=4 per iteration, 256-thread blocks, 8 blocks/SM.
// ---------------------------------------------------------------------------
__device__ __forceinline__ float2 edge_prob_q(int q)
{
    const float d   = (float)q * QINV;
    const float t   = __expf(-d);
    const float inv = 1.0f / (1.0f + t);
    return make_float2(inv, t * inv);   // (p0, p1)
}

__device__ __forceinline__ int clampN(int v, int nclamp)
{
    return min(max(v, 0), nclamp);
}

__global__ __launch_bounds__(256)
void edge_softmax_kernel(const void* __restrict__ ei_raw,
                         float4* __restrict__ out4,  // [E/2] float4 = [E,2] f32
                         int n_edges, int n_nodes)
{
    const int tid0     = (int)(blockIdx.x * (unsigned)blockDim.x + threadIdx.x);
    const int n_thr    = GRID_BLKS * 256;
    const int n_groups = (n_edges + EPT - 1) / EPT;
    const int nclamp   = n_nodes - 1;
    const int is64     = g_idx_is64;

    for (int g = tid0; g < n_groups; g += n_thr) {
        const int e0 = g * EPT;

        if (e0 + EPT <= n_edges) {
            int r[EPT], c[EPT];
            if (is64) {
                const longlong2* eiR = (const longlong2*)ei_raw + (e0 >> 1);
                const longlong2* eiC = (const longlong2*)((const char*)ei_raw + (size_t)n_edges * 8) + (e0 >> 1);
#pragma unroll
                for (int j = 0; j < EPT / 2; j++) {
                    const longlong2 rv = eiR[j];
                    const longlong2 cv = eiC[j];
                    r[2*j] = (int)rv.x; r[2*j+1] = (int)rv.y;
                    c[2*j] = (int)cv.x; c[2*j+1] = (int)cv.y;
                }
            } else {
                const int4 rv = *(const int4*)((const int*)ei_raw + e0);
                const int4 cv = *(const int4*)((const int*)ei_raw + n_edges + e0);
                r[0] = rv.x; r[1] = rv.y; r[2] = rv.z; r[3] = rv.w;
                c[0] = cv.x; c[1] = cv.y; c[2] = cv.z; c[3] = cv.w;
            }

            // Issue all 2*EPT independent gathers before consuming (max MLP).
            unsigned int ur[EPT], uc[EPT];
#pragma unroll
            for (int i = 0; i < EPT; i++) ur[i] = __ldg(&g_dS[clampN(r[i], nclamp)]);
#pragma unroll
            for (int i = 0; i < EPT; i++) uc[i] = __ldg(&g_dS[clampN(c[i], nclamp)]);

#pragma unroll
            for (int j = 0; j < EPT / 2; j++) {
                // q = qA[r] (low 16, sign-ext) + qB[c] (high 16, arithmetic >>)
                const int q0 = (int)(short)(ur[2*j]   & 0xFFFFu) + ((int)uc[2*j]   >> 16);
                const int q1 = (int)(short)(ur[2*j+1] & 0xFFFFu) + ((int)uc[2*j+1] >> 16);
                const float2 p0 = edge_prob_q(q0);
                const float2 p1 = edge_prob_q(q1);
                out4[(size_t)(e0 >> 1) + j] = make_float4(p0.x, p0.y, p1.x, p1.y);
            }
        } else {
            // Tail group: scalar path
            float2* out2 = (float2*)out4;
            for (int e = e0; e < n_edges; e++) {
                int rr, cc;
                if (is64) {
                    const long long* ei = (const long long*)ei_raw;
                    rr = (int)ei[e];
                    cc = (int)ei[n_edges + e];
                } else {
                    const int* ei = (const int*)ei_raw;
                    rr = ei[e];
                    cc = ei[n_edges + e];
                }
                const unsigned int a = __ldg(&g_dS[clampN(rr, nclamp)]);
                const unsigned int b = __ldg(&g_dS[clampN(cc, nclamp)]);
                const int q = (int)(short)(a & 0xFFFFu) + ((int)b >> 16);
                out2[e] = edge_prob_q(q);
            }
        }
    }
}

// ---------------------------------------------------------------------------
extern "C" void kernel_launch(void* const* d_in, const int* in_sizes, int n_in,
                              void* d_out, int out_size)
{
    // Bind inputs by element count (all four are distinct):
    //   node_embeddings: N*128 (largest), edge_index: 2*E, W: 512, b: 2
    const float* emb  = nullptr; int emb_elems = 0;
    const void*  ei   = nullptr; int ei_elems  = 0;
    const float* W    = nullptr;
    const float* bias = nullptr;

    int i_emb = -1, i_ei = -1;
    for (int i = 0; i < n_in; i++) {
        if (i_emb < 0 || in_sizes[i] > in_sizes[i_emb]) i_emb = i;
    }
    for (int i = 0; i < n_in; i++) {
        if (i == i_emb) continue;
        if (i_ei < 0 || in_sizes[i] > in_sizes[i_ei]) i_ei = i;
    }
    emb = (const float*)d_in[i_emb]; emb_elems = in_sizes[i_emb];
    ei  = d_in[i_ei];                ei_elems  = in_sizes[i_ei];
    for (int i = 0; i < n_in; i++) {
        if (i == i_emb || i == i_ei) continue;
        if (in_sizes[i] > 16) W = (const float*)d_in[i];    // 512 elems
        else                  bias = (const float*)d_in[i]; // 2 elems
    }
    if (!W    && n_in > 2) W    = (const float*)d_in[2];
    if (!bias && n_in > 3) bias = (const float*)d_in[3];

    const int n_nodes = emb_elems / D_FEAT;
    const int n_edges = ei_elems / 2;

    // Kernel 1: grid-stride, exactly one full residency wave (1184 blocks)
    node_scores_kernel<<<GRID_BLKS, 256>>>(
        (const float4*)emb, W, bias, (const unsigned int*)ei, n_nodes);

    // Kernel 2: grid-stride, exactly one full residency wave (1184 blocks)
    edge_softmax_kernel<<<GRID_BLKS, 256>>>(ei, (float4*)d_out,
                                            n_edges, n_nodes);
}

// round 13
// speedup vs baseline: 1.0090x; 1.0090x over previous
#include <cuda_runtime.h>
#include <cuda_bf16.h>
#include <cstdint>

// Problem constants (fixed by the dataset)
#define MAX_NODES 100000
#define D_FEAT    128
#define NPW       8       // nodes per warp-iteration in kernel 1
#define EPT       4       // edges per thread in kernel 2 (best measured)
#define NODE_BLKS 1184    // 148 SMs x 8 resident 256-thr blocks
#define QSCALE    4096.0f
#define QINV      (1.0f / 4096.0f)

// Quantized per-node logit-difference table (sigmoid reformulation):
//   dA[n] = emb[n].(W0-W1)[0:128] + (b0-b1),  dB[n] = emb[n].(W0-W1)[128:256]
//   g_dS[n] = (int16 round(dA*4096), int16 round(dB*4096)) packed in 4 bytes.
// Edge e=(r,c): q = qA[r]+qB[c] (exact int), d = q/4096,
//   p0 = 1/(1+exp(-d)), p1 = exp(-d)/(1+exp(-d)).
// Quantization rel err on p ~3e-5 (measured R10-R12).
__device__ unsigned int g_dS[MAX_NODES];

// 1 if edge_index buffer holds int64 elements, 0 if int32.
__device__ int g_idx_is64;

// ---------------------------------------------------------------------------
// Kernel 1: grid-stride; each warp-iteration computes NPW nodes. Lane k owns
// columns 4k..4k+3 (one LDG.128 per node, MLP=NPW). Wd = W0-W1 in smem
// (conflict-free float4 reads). 7-shuffle dual reduction, even lane packs.
// Block 0 / thread 0 also performs the index-dtype detection.
// ---------------------------------------------------------------------------
__global__ __launch_bounds__(256)
void node_scores_kernel(const float4* __restrict__ emb4,
                        const float* __restrict__ W,
                        const float* __restrict__ bias,
                        const unsigned int* __restrict__ idx_words,
                        int n_nodes)
{
    __shared__ __align__(16) float Wd[256];   // W0 - W1, 256 floats
    for (int i = threadIdx.x; i < 256; i += blockDim.x)
        Wd[i] = W[i] - W[256 + i];
    __syncthreads();

    // Index-dtype detection: little-endian int64 ids < 100000 have all odd
    // 32-bit words zero; int32 data has random ids there (P ~ 1e-160).
    if (blockIdx.x == 0 && threadIdx.x == 0) {
        unsigned int acc = 0;
#pragma unroll
        for (int i = 1; i < 64; i += 2) acc |= idx_words[i];
        g_idx_is64 = (acc == 0u) ? 1 : 0;
    }

    const int lane     = threadIdx.x & 31;
    const int warp_g   = (int)((blockIdx.x * (unsigned)blockDim.x + threadIdx.x) >> 5);
    const int n_warps  = (NODE_BLKS * 256) >> 5;
    const int n_groups = (n_nodes + NPW - 1) / NPW;

    const float dbias = bias[0] - bias[1];

    const float4* wd4 = (const float4*)Wd;
    const float4 wsrc = wd4[lane];        // (W0-W1)[4k..4k+3]
    const float4 wdst = wd4[32 + lane];   // (W0-W1)[128+4k..128+4k+3]

    for (int grp = warp_g; grp < n_groups; grp += n_warps) {
        const int node0 = grp * NPW;

        // Batch the independent embedding loads first (MLP = NPW).
        float4 v[NPW];
#pragma unroll
        for (int i = 0; i < NPW; i++) {
            const int n = node0 + i;
            v[i] = (n < n_nodes) ? __ldg(&emb4[(size_t)n * 32 + lane])
                                 : make_float4(0.f, 0.f, 0.f, 0.f);
        }

#pragma unroll
        for (int i = 0; i < NPW; i++) {
            float da = v[i].x * wsrc.x;
            da = fmaf(v[i].y, wsrc.y, da);
            da = fmaf(v[i].z, wsrc.z, da);
            da = fmaf(v[i].w, wsrc.w, da);
            float db = v[i].x * wdst.x;
            db = fmaf(v[i].y, wdst.y, db);
            db = fmaf(v[i].z, wdst.z, db);
            db = fmaf(v[i].w, wdst.w, db);

            // Dual reduction: even lanes end with da, odd lanes with db.
            da += __shfl_xor_sync(0xFFFFFFFFu, da, 1);
            db += __shfl_xor_sync(0xFFFFFFFFu, db, 1);
            float sel = (lane & 1) ? db : da;
            sel += __shfl_xor_sync(0xFFFFFFFFu, sel, 2);
            sel += __shfl_xor_sync(0xFFFFFFFFu, sel, 4);
            sel += __shfl_xor_sync(0xFFFFFFFFu, sel, 8);
            sel += __shfl_xor_sync(0xFFFFFFFFu, sel, 16);

            // Bring odd lane's db to the even lane, quantize, pack, store.
            const float other = __shfl_xor_sync(0xFFFFFFFFu, sel, 1);
            const int n = node0 + i;
            if (lane == 2 * i && n < n_nodes) {
                const float dA = sel + dbias;    // even lane held da
                const float dB = other;          // odd lane held db
                int qa = __float2int_rn(fminf(fmaxf(dA * QSCALE, -32767.f), 32767.f));
                int qb = __float2int_rn(fminf(fmaxf(dB * QSCALE, -32767.f), 32767.f));
                g_dS[n] = ((unsigned int)qa & 0xFFFFu) | ((unsigned int)qb << 16);
            }
        }
    }
}

// ---------------------------------------------------------------------------
// Kernel 2: per-edge gather from the 400KB packed table + sigmoid.
// Fixed grid, EPT=4, 256-thr (best measured: 19.0us in R11).
// Streaming flows (index reads, output writes) use evict-first cache policy
// (__ldcs/__stcs) so L1 capacity is reserved for the gather table.
// ---------------------------------------------------------------------------
__device__ __forceinline__ float2 edge_prob_q(int q)
{
    const float d   = (float)q * QINV;
    const float t   = __expf(-d);
    const float inv = 1.0f / (1.0f + t);
    return make_float2(inv, t * inv);   // (p0, p1)
}

__device__ __forceinline__ int clampN(int v, int nclamp)
{
    return min(max(v, 0), nclamp);
}

__global__ __launch_bounds__(256)
void edge_softmax_kernel(const void* __restrict__ ei_raw,
                         float4* __restrict__ out4,  // [E/2] float4 = [E,2] f32
                         int n_edges, int n_nodes)
{
    const int t  = (int)(blockIdx.x * (unsigned)blockDim.x + threadIdx.x);
    const int e0 = t * EPT;
    if (e0 >= n_edges) return;

    const int nclamp = n_nodes - 1;

    if (e0 + EPT <= n_edges) {
        int r[EPT], c[EPT];
        if (g_idx_is64) {
            const longlong2* eiR = (const longlong2*)ei_raw + (e0 >> 1);
            const longlong2* eiC = (const longlong2*)((const char*)ei_raw + (size_t)n_edges * 8) + (e0 >> 1);
#pragma unroll
            for (int j = 0; j < EPT / 2; j++) {
                const longlong2 rv = __ldcs(&eiR[j]);
                const longlong2 cv = __ldcs(&eiC[j]);
                r[2*j] = (int)rv.x; r[2*j+1] = (int)rv.y;
                c[2*j] = (int)cv.x; c[2*j+1] = (int)cv.y;
            }
        } else {
            const int4 rv = __ldcs((const int4*)((const int*)ei_raw + e0));
            const int4 cv = __ldcs((const int4*)((const int*)ei_raw + n_edges + e0));
            r[0] = rv.x; r[1] = rv.y; r[2] = rv.z; r[3] = rv.w;
            c[0] = cv.x; c[1] = cv.y; c[2] = cv.z; c[3] = cv.w;
        }

        // Issue all 2*EPT independent gathers before consuming (max MLP).
        unsigned int ur[EPT], uc[EPT];
#pragma unroll
        for (int i = 0; i < EPT; i++) ur[i] = __ldg(&g_dS[clampN(r[i], nclamp)]);
#pragma unroll
        for (int i = 0; i < EPT; i++) uc[i] = __ldg(&g_dS[clampN(c[i], nclamp)]);

#pragma unroll
        for (int j = 0; j < EPT / 2; j++) {
            // q = qA[r] (low 16, sign-ext) + qB[c] (high 16, arithmetic >>)
            const int q0 = (int)(short)(ur[2*j]   & 0xFFFFu) + ((int)uc[2*j]   >> 16);
            const int q1 = (int)(short)(ur[2*j+1] & 0xFFFFu) + ((int)uc[2*j+1] >> 16);
            const float2 p0 = edge_prob_q(q0);
            const float2 p1 = edge_prob_q(q1);
            __stcs(&out4[(size_t)t * (EPT / 2) + j],
                   make_float4(p0.x, p0.y, p1.x, p1.y));
        }
    } else {
        // Tail: scalar path
        float2* out2 = (float2*)out4;
        for (int e = e0; e < n_edges; e++) {
            int rr, cc;
            if (g_idx_is64) {
                const long long* ei = (const long long*)ei_raw;
                rr = (int)ei[e];
                cc = (int)ei[n_edges + e];
            } else {
                const int* ei = (const int*)ei_raw;
                rr = ei[e];
                cc = ei[n_edges + e];
            }
            const unsigned int a = __ldg(&g_dS[clampN(rr, nclamp)]);
            const unsigned int b = __ldg(&g_dS[clampN(cc, nclamp)]);
            const int q = (int)(short)(a & 0xFFFFu) + ((int)b >> 16);
            out2[e] = edge_prob_q(q);
        }
    }
}

// ---------------------------------------------------------------------------
extern "C" void kernel_launch(void* const* d_in, const int* in_sizes, int n_in,
                              void* d_out, int out_size)
{
    // Bind inputs by element count (all four are distinct):
    //   node_embeddings: N*128 (largest), edge_index: 2*E, W: 512, b: 2
    const float* emb  = nullptr; int emb_elems = 0;
    const void*  ei   = nullptr; int ei_elems  = 0;
    const float* W    = nullptr;
    const float* bias = nullptr;

    int i_emb = -1, i_ei = -1;
    for (int i = 0; i < n_in; i++) {
        if (i_emb < 0 || in_sizes[i] > in_sizes[i_emb]) i_emb = i;
    }
    for (int i = 0; i < n_in; i++) {
        if (i == i_emb) continue;
        if (i_ei < 0 || in_sizes[i] > in_sizes[i_ei]) i_ei = i;
    }
    emb = (const float*)d_in[i_emb]; emb_elems = in_sizes[i_emb];
    ei  = d_in[i_ei];                ei_elems  = in_sizes[i_ei];
    for (int i = 0; i < n_in; i++) {
        if (i == i_emb || i == i_ei) continue;
        if (in_sizes[i] > 16) W = (const float*)d_in[i];    // 512 elems
        else                  bias = (const float*)d_in[i]; // 2 elems
    }
    if (!W    && n_in > 2) W    = (const float*)d_in[2];
    if (!bias && n_in > 3) bias = (const float*)d_in[3];

    const int n_nodes = emb_elems / D_FEAT;
    const int n_edges = ei_elems / 2;

    // Kernel 1: grid-stride, one full residency wave (measured best in R12)
    node_scores_kernel<<<NODE_BLKS, 256>>>(
        (const float4*)emb, W, bias, (const unsigned int*)ei, n_nodes);

    // Kernel 2: fixed grid, 4 edges/thread (measured best in R11)
    {
        const int threads = 256;
        const int edges_per_block = threads * EPT;
        const int blocks = (n_edges + edges_per_block - 1) / edges_per_block;
        edge_softmax_kernel<<<blocks, threads>>>(ei, (float4*)d_out,
                                                 n_edges, n_nodes);
    }
}

// round 14
// speedup vs baseline: 1.0666x; 1.0571x over previous
#include <cuda_runtime.h>
#include <cuda_bf16.h>
#include <cstdint>

// Problem constants (fixed by the dataset)
#define MAX_NODES 100000
#define D_FEAT    128
#define NPW       8       // nodes per warp-iteration in kernel 1
#define EPT       4       // edges per thread in kernel 2 (best measured)
#define NODE_BLKS 1184    // 148 SMs x 8 resident 256-thr blocks
#define QSCALE    4096.0f
#define QINV      (1.0f / 4096.0f)

// Quantized per-node logit-difference table (sigmoid reformulation):
//   dA[n] = emb[n].(W0-W1)[0:128] + (b0-b1),  dB[n] = emb[n].(W0-W1)[128:256]
//   g_dS[n] = (int16 round(dA*4096), int16 round(dB*4096)) packed in 4 bytes.
// Edge e=(r,c): q = qA[r]+qB[c] (exact int), d = q/4096,
//   p0 = 1/(1+exp(-d)), p1 = exp(-d)/(1+exp(-d)).
// Quantization rel err on p ~3e-5 (measured R10-R12).
__device__ unsigned int g_dS[MAX_NODES];

// 1 if edge_index buffer holds int64 elements, 0 if int32.
__device__ int g_idx_is64;

// ---------------------------------------------------------------------------
// Kernel 1: grid-stride; each warp-iteration computes NPW nodes. Lane k owns
// columns 4k..4k+3 (one LDG.128 per node, MLP=NPW). Wd = W0-W1 in smem
// (conflict-free float4 reads). 7-shuffle dual reduction, even lane packs.
// Block 0 / thread 0 also performs the index-dtype detection.
// ---------------------------------------------------------------------------
__global__ __launch_bounds__(256)
void node_scores_kernel(const float4* __restrict__ emb4,
                        const float* __restrict__ W,
                        const float* __restrict__ bias,
                        const unsigned int* __restrict__ idx_words,
                        int n_nodes)
{
    __shared__ __align__(16) float Wd[256];   // W0 - W1, 256 floats
    for (int i = threadIdx.x; i < 256; i += blockDim.x)
        Wd[i] = W[i] - W[256 + i];
    __syncthreads();

    // Index-dtype detection: little-endian int64 ids < 100000 have all odd
    // 32-bit words zero; int32 data has random ids there (P ~ 1e-160).
    if (blockIdx.x == 0 && threadIdx.x == 0) {
        unsigned int acc = 0;
#pragma unroll
        for (int i = 1; i < 64; i += 2) acc |= idx_words[i];
        g_idx_is64 = (acc == 0u) ? 1 : 0;
    }

    const int lane     = threadIdx.x & 31;
    const int warp_g   = (int)((blockIdx.x * (unsigned)blockDim.x + threadIdx.x) >> 5);
    const int n_warps  = (NODE_BLKS * 256) >> 5;
    const int n_groups = (n_nodes + NPW - 1) / NPW;

    const float dbias = bias[0] - bias[1];

    const float4* wd4 = (const float4*)Wd;
    const float4 wsrc = wd4[lane];        // (W0-W1)[4k..4k+3]
    const float4 wdst = wd4[32 + lane];   // (W0-W1)[128+4k..128+4k+3]

    for (int grp = warp_g; grp < n_groups; grp += n_warps) {
        const int node0 = grp * NPW;

        // Batch the independent embedding loads first (MLP = NPW).
        float4 v[NPW];
#pragma unroll
        for (int i = 0; i < NPW; i++) {
            const int n = node0 + i;
            v[i] = (n < n_nodes) ? __ldg(&emb4[(size_t)n * 32 + lane])
                                 : make_float4(0.f, 0.f, 0.f, 0.f);
        }

#pragma unroll
        for (int i = 0; i < NPW; i++) {
            float da = v[i].x * wsrc.x;
            da = fmaf(v[i].y, wsrc.y, da);
            da = fmaf(v[i].z, wsrc.z, da);
            da = fmaf(v[i].w, wsrc.w, da);
            float db = v[i].x * wdst.x;
            db = fmaf(v[i].y, wdst.y, db);
            db = fmaf(v[i].z, wdst.z, db);
            db = fmaf(v[i].w, wdst.w, db);

            // Dual reduction: even lanes end with da, odd lanes with db.
            da += __shfl_xor_sync(0xFFFFFFFFu, da, 1);
            db += __shfl_xor_sync(0xFFFFFFFFu, db, 1);
            float sel = (lane & 1) ? db : da;
            sel += __shfl_xor_sync(0xFFFFFFFFu, sel, 2);
            sel += __shfl_xor_sync(0xFFFFFFFFu, sel, 4);
            sel += __shfl_xor_sync(0xFFFFFFFFu, sel, 8);
            sel += __shfl_xor_sync(0xFFFFFFFFu, sel, 16);

            // Bring odd lane's db to the even lane, quantize, pack, store.
            const float other = __shfl_xor_sync(0xFFFFFFFFu, sel, 1);
            const int n = node0 + i;
            if (lane == 2 * i && n < n_nodes) {
                const float dA = sel + dbias;    // even lane held da
                const float dB = other;          // odd lane held db
                int qa = __float2int_rn(fminf(fmaxf(dA * QSCALE, -32767.f), 32767.f));
                int qb = __float2int_rn(fminf(fmaxf(dB * QSCALE, -32767.f), 32767.f));
                g_dS[n] = ((unsigned int)qa & 0xFFFFu) | ((unsigned int)qb << 16);
            }
        }
    }
}

// ---------------------------------------------------------------------------
// Kernel 2: per-edge gather from the 400KB packed table + sigmoid.
// Fixed grid, EPT=4, 256-thr (best measured: 19.0us in R11).
// Streaming flows (index reads, output writes) use evict-first cache policy
// (__ldcs/__stcs) so L1 capacity is reserved for the gather table.
// ---------------------------------------------------------------------------
__device__ __forceinline__ float2 edge_prob_q(int q)
{
    const float d   = (float)q * QINV;
    const float t   = __expf(-d);
    const float inv = 1.0f / (1.0f + t);
    return make_float2(inv, t * inv);   // (p0, p1)
}

__device__ __forceinline__ int clampN(int v, int nclamp)
{
    return min(max(v, 0), nclamp);
}

__global__ __launch_bounds__(256)
void edge_softmax_kernel(const void* __restrict__ ei_raw,
                         float4* __restrict__ out4,  // [E/2] float4 = [E,2] f32
                         int n_edges, int n_nodes)
{
    const int t  = (int)(blockIdx.x * (unsigned)blockDim.x + threadIdx.x);
    const int e0 = t * EPT;
    if (e0 >= n_edges) return;

    const int nclamp = n_nodes - 1;

    if (e0 + EPT <= n_edges) {
        int r[EPT], c[EPT];
        if (g_idx_is64) {
            const longlong2* eiR = (const longlong2*)ei_raw + (e0 >> 1);
            const longlong2* eiC = (const longlong2*)((const char*)ei_raw + (size_t)n_edges * 8) + (e0 >> 1);
#pragma unroll
            for (int j = 0; j < EPT / 2; j++) {
                const longlong2 rv = __ldcs(&eiR[j]);
                const longlong2 cv = __ldcs(&eiC[j]);
                r[2*j] = (int)rv.x; r[2*j+1] = (int)rv.y;
                c[2*j] = (int)cv.x; c[2*j+1] = (int)cv.y;
            }
        } else {
            const int4 rv = __ldcs((const int4*)((const int*)ei_raw + e0));
            const int4 cv = __ldcs((const int4*)((const int*)ei_raw + n_edges + e0));
            r[0] = rv.x; r[1] = rv.y; r[2] = rv.z; r[3] = rv.w;
            c[0] = cv.x; c[1] = cv.y; c[2] = cv.z; c[3] = cv.w;
        }

        // Issue all 2*EPT independent gathers before consuming (max MLP).
        unsigned int ur[EPT], uc[EPT];
#pragma unroll
        for (int i = 0; i < EPT; i++) ur[i] = __ldg(&g_dS[clampN(r[i], nclamp)]);
#pragma unroll
        for (int i = 0; i < EPT; i++) uc[i] = __ldg(&g_dS[clampN(c[i], nclamp)]);

#pragma unroll
        for (int j = 0; j < EPT / 2; j++) {
            // q = qA[r] (low 16, sign-ext) + qB[c] (high 16, arithmetic >>)
            const int q0 = (int)(short)(ur[2*j]   & 0xFFFFu) + ((int)uc[2*j]   >> 16);
            const int q1 = (int)(short)(ur[2*j+1] & 0xFFFFu) + ((int)uc[2*j+1] >> 16);
            const float2 p0 = edge_prob_q(q0);
            const float2 p1 = edge_prob_q(q1);
            __stcs(&out4[(size_t)t * (EPT / 2) + j],
                   make_float4(p0.x, p0.y, p1.x, p1.y));
        }
    } else {
        // Tail: scalar path
        float2* out2 = (float2*)out4;
        for (int e = e0; e < n_edges; e++) {
            int rr, cc;
            if (g_idx_is64) {
                const long long* ei = (const long long*)ei_raw;
                rr = (int)ei[e];
                cc = (int)ei[n_edges + e];
            } else {
                const int* ei = (const int*)ei_raw;
                rr = ei[e];
                cc = ei[n_edges + e];
            }
            const unsigned int a = __ldg(&g_dS[clampN(rr, nclamp)]);
            const unsigned int b = __ldg(&g_dS[clampN(cc, nclamp)]);
            const int q = (int)(short)(a & 0xFFFFu) + ((int)b >> 16);
            out2[e] = edge_prob_q(q);
        }
    }
}

// ---------------------------------------------------------------------------
extern "C" void kernel_launch(void* const* d_in, const int* in_sizes, int n_in,
                              void* d_out, int out_size)
{
    // Bind inputs by element count (all four are distinct):
    //   node_embeddings: N*128 (largest), edge_index: 2*E, W: 512, b: 2
    const float* emb  = nullptr; int emb_elems = 0;
    const void*  ei   = nullptr; int ei_elems  = 0;
    const float* W    = nullptr;
    const float* bias = nullptr;

    int i_emb = -1, i_ei = -1;
    for (int i = 0; i < n_in; i++) {
        if (i_emb < 0 || in_sizes[i] > in_sizes[i_emb]) i_emb = i;
    }
    for (int i = 0; i < n_in; i++) {
        if (i == i_emb) continue;
        if (i_ei < 0 || in_sizes[i] > in_sizes[i_ei]) i_ei = i;
    }
    emb = (const float*)d_in[i_emb]; emb_elems = in_sizes[i_emb];
    ei  = d_in[i_ei];                ei_elems  = in_sizes[i_ei];
    for (int i = 0; i < n_in; i++) {
        if (i == i_emb || i == i_ei) continue;
        if (in_sizes[i] > 16) W = (const float*)d_in[i];    // 512 elems
        else                  bias = (const float*)d_in[i]; // 2 elems
    }
    if (!W    && n_in > 2) W    = (const float*)d_in[2];
    if (!bias && n_in > 3) bias = (const float*)d_in[3];

    const int n_nodes = emb_elems / D_FEAT;
    const int n_edges = ei_elems / 2;

    // Kernel 1: grid-stride, one full residency wave (measured best in R12)
    node_scores_kernel<<<NODE_BLKS, 256>>>(
        (const float4*)emb, W, bias, (const unsigned int*)ei, n_nodes);

    // Kernel 2: fixed grid, 4 edges/thread (measured best in R11)
    {
        const int threads = 256;
        const int edges_per_block = threads * EPT;
        const int blocks = (n_edges + edges_per_block - 1) / edges_per_block;
        edge_softmax_kernel<<<blocks, threads>>>(ei, (float4*)d_out,
                                                 n_edges, n_nodes);
    }
}